// round 13
// baseline (speedup 1.0000x reference)
#include <cuda_runtime.h>
#include <cuda_bf16.h>

#define KNN   32
#define MAXC  128          // per-warp candidate cap (in-cutoff mean ~34)
#define NB    50           // z-bins per strip (width = 1.0)
#define NYB   5            // y-strips (width = 10.0)
#define NCB   (NYB * NB)   // bins per segment = 250
#define NSEG  8
#define GBINS (NSEG * NCB) // global bins = 2000
#define NMAX  8192
#define WPB   8            // worker warps per block (256 threads)
#define PREPB 32           // prep blocks (co-resident, barrier-safe)

__device__ float4 g_pq [NMAX];          // original order: (p0,p1,p2,|p|^2)
__device__ float4 g_pqs[NMAX];          // globally bin-sorted
__device__ int    g_oidx[NMAX];         // sorted position -> original index
__device__ int    g_hist[GBINS];        // zeroed at load; re-zeroed each run
__device__ int    g_cum[GBINS + 1];     // absolute exclusive bin starts
__device__ int    g_cursor[GBINS];      // scatter cursors (rewritten each run)
__device__ int    g_bar_count;          // barrier arrivals (self-resetting)
__device__ int    g_bar_gen;            // barrier generation (monotonic)

__device__ __forceinline__ int z_bin(float z) {
    return min(NB - 1, max(0, (int)(z)));            // width 1.0
}
__device__ __forceinline__ int y_strip(float y) {
    return min(NYB - 1, max(0, (int)(y * 0.1f)));    // width 10.0
}
__device__ __forceinline__ int node_bin(int b, float y, float z) {
    return b * NCB + y_strip(y) * NB + z_bin(z);
}

// Monotonic float->uint (handles tiny negative d2 from gram-trick rounding)
__device__ __forceinline__ unsigned int f2mono(float f) {
    unsigned int u = __float_as_uint(f);
    return (u & 0x80000000u) ? ~u : (u | 0x80000000u);
}

__device__ __forceinline__ int ld_acquire(int* p) {
    int v;
    asm volatile("ld.acquire.gpu.s32 %0, [%1];" : "=r"(v) : "l"(p) : "memory");
    return v;
}

// Grid barrier for PREPB co-resident blocks. TIGHT spin (no nanosleep): only
// 32 threads poll -> negligible L2 traffic, minimal release latency.
// Generation counter is monotonic (no reset -> replay-deterministic).
__device__ __forceinline__ void grid_barrier() {
    __syncthreads();
    if (threadIdx.x == 0) {
        int gen = ld_acquire(&g_bar_gen);
        __threadfence();
        int v = atomicAdd(&g_bar_count, 1);
        if (v == PREPB - 1) {
            g_bar_count = 0;
            __threadfence();
            atomicAdd(&g_bar_gen, 1);
        } else {
            while (ld_acquire(&g_bar_gen) == gen) { }
        }
    }
    __syncthreads();
}

// ---------------- Kernel 1: fused hist -> scan -> scatter (32 blocks x 256).
__global__ void __launch_bounds__(256)
prep_kernel(const float* __restrict__ pos,
            const int* __restrict__ batch, int N) {
    const int tid  = threadIdx.x;
    const int lane = tid & 31;
    const int wid  = tid >> 5;
    const int gi   = blockIdx.x * 256 + tid;

    int   mybin = -1;
    float4 mypq;

    // --- phase A: pack (pos,|p|^2) with reference rounding + global histogram
    if (gi < N) {
        float p0 = pos[3*gi+0], p1 = pos[3*gi+1], p2 = pos[3*gi+2];
        float a = __fadd_rn(__fadd_rn(__fmul_rn(p0,p0), __fmul_rn(p1,p1)),
                            __fmul_rn(p2,p2));
        mypq  = make_float4(p0, p1, p2, a);
        mybin = node_bin(batch[gi], p1, p2);
        g_pq[gi] = mypq;
        atomicAdd(&g_hist[mybin], 1);
    }
    __threadfence();
    grid_barrier();

    // --- phase B: block 0 scans 2000 bins (8 bins/thread, int4-vectorized),
    // seeds cursors, re-zeroes hist. Other blocks tight-spin at barrier 2.
    if (blockIdx.x == 0) {
        __shared__ int s_part[8];
        const int bbase = tid * 8;
        int4 ha = *reinterpret_cast<const int4*>(&g_hist[bbase]);
        int4 hb = *reinterpret_cast<const int4*>(&g_hist[bbase + 4]);
        int h[8] = {ha.x, ha.y, ha.z, ha.w, hb.x, hb.y, hb.z, hb.w};
        int tot = h[0]+h[1]+h[2]+h[3]+h[4]+h[5]+h[6]+h[7];

        int incl = tot;
        #pragma unroll
        for (int o = 1; o < 32; o <<= 1) {
            int v = __shfl_up_sync(0xffffffffu, incl, o);
            if (lane >= o) incl += v;
        }
        if (lane == 31) s_part[wid] = incl;
        __syncthreads();
        int off = 0;
        #pragma unroll
        for (int p = 0; p < 8; p++) off += (p < wid) ? s_part[p] : 0;
        int run = off + incl - tot;           // exclusive start for this thread
        #pragma unroll
        for (int k = 0; k < 8; k++) {
            int bin = bbase + k;
            g_cum[bin]    = run;
            g_cursor[bin] = run;
            g_hist[bin]   = 0;                // ready for next replay
            run += h[k];
        }
        if (tid == 255) g_cum[GBINS] = run;   // == N
        __threadfence();
    }
    grid_barrier();

    // --- phase C: scatter into globally sorted order (in-bin order
    // nondeterministic -- output-invariant, keys carry original index)
    if (gi < N) {
        int slot = atomicAdd(&g_cursor[mybin], 1);
        g_pqs [slot] = mypq;
        g_oidx[slot] = gi;
    }
}

// ---------------- Kernel 2: one WARP per SORTED position (identical to R11/R12).
__global__ void __launch_bounds__(WPB * 32)
radius_graph_kernel(const int* __restrict__ batch,
                    float* __restrict__ out, int N) {
    __shared__ unsigned long long s_keys[WPB][MAXC];
    __shared__ unsigned long long s_sel [WPB][KNN];

    const int w    = threadIdx.x >> 5;
    const int lane = threadIdx.x & 31;
    const int s    = blockIdx.x * WPB + w;     // sorted position
    if (s >= N) return;                         // no block-level syncs below

    const int b  = batch[s];        // global sort keeps segments contiguous
    const int cb = b * NCB;

    const float4 pc = g_pqs[s];     // same bits as g_pq[i]
    const int   i  = g_oidx[s];     // original node index
    const float p0 = pc.x, p1 = pc.y, p2 = pc.z, x2i = pc.w;

    // (y,z) bin ranges covering [+-10.01]: over-coverage strictly dominates
    // gram-trick rounding slack AND bin-boundary fp edges -> no false prunes.
    int bzlo = max(0,      (int)floorf(p2 - 10.01f));
    int bzhi = min(NB - 1, (int)floorf(p2 + 10.01f));
    int yslo = max(0,       (int)floorf((p1 - 10.01f) * 0.1f));
    int yshi = min(NYB - 1, (int)floorf((p1 + 10.01f) * 0.1f));

    // Phase 1: dual-candidate scan (64/warp-iter, MLP=2, 2 ballots).
    // Compaction order is irrelevant: keys unique, rank-select is a total order.
    int base = 0;
    for (int ys = yslo; ys <= yshi; ys++) {
        const int rlo = g_cum[cb + ys * NB + bzlo];       // absolute positions
        const int rhi = g_cum[cb + ys * NB + bzhi + 1];
        for (int rb = rlo; rb < rhi; rb += 64) {
            int r0 = rb + lane, r1 = rb + 32 + lane;
            int rc0 = min(r0, rhi - 1), rc1 = min(r1, rhi - 1);
            float4 q0 = g_pqs[rc0];
            float4 q1 = g_pqs[rc1];
            int   o0 = g_oidx[rc0];
            int   o1 = g_oidx[rc1];
            // d2 = (x2i + x2j) - 2*dot, exact reference rounding
            float dot0 = __fmaf_rn(p2, q0.z, __fmaf_rn(p1, q0.y, __fmul_rn(p0, q0.x)));
            float d20  = __fsub_rn(__fadd_rn(x2i, q0.w), __fmul_rn(2.0f, dot0));
            float dot1 = __fmaf_rn(p2, q1.z, __fmaf_rn(p1, q1.y, __fmul_rn(p0, q1.x)));
            float d21  = __fsub_rn(__fadd_rn(x2i, q1.w), __fmul_rn(2.0f, dot1));
            bool h0 = (r0 < rhi) && (d20 <= 100.0f) && (o0 != i);
            bool h1 = (r1 < rhi) && (d21 <= 100.0f) && (o1 != i);
            unsigned m0 = __ballot_sync(0xffffffffu, h0);
            unsigned m1 = __ballot_sync(0xffffffffu, h1);
            int c0 = __popc(m0);
            if (h0) {
                int slot = base + __popc(m0 & ((1u << lane) - 1u));
                if (slot < MAXC)
                    s_keys[w][slot] = ((unsigned long long)f2mono(d20) << 32)
                                    | (unsigned int)o0;
            }
            if (h1) {
                int slot = base + c0 + __popc(m1 & ((1u << lane) - 1u));
                if (slot < MAXC)
                    s_keys[w][slot] = ((unsigned long long)f2mono(d21) << 32)
                                    | (unsigned int)o1;
            }
            base += c0 + __popc(m1);
        }
    }
    const int M = min(base, MAXC);
    __syncwarp();

    // Phase 2: exact rank selection (keys unique; tie -> lower index, = lax.top_k)
    for (int e = lane; e < M; e += 32) {
        unsigned long long mykey = s_keys[w][e];
        int rank = 0;
        #pragma unroll 4
        for (int t = 0; t < M; t++) rank += (s_keys[w][t] < mykey) ? 1 : 0;
        if (rank < KNN) s_sel[w][rank] = mykey;
    }
    __syncwarp();

    const int Msel = min(M, KNN);
    const long long E = (long long)N * (KNN + 1);

    // Phase 3: lane k writes neighbor slot k (K == warp size)
    {
        const int k = lane;
        long long e = (long long)i * KNN + k;
        float rowf = 0.0f, wgt = 0.0f, mf = 0.0f;
        if (k < Msel) {
            unsigned long long key = s_sel[w][k];
            int j = (int)(key & 0xFFFFFFFFull);
            rowf = (float)j;
            mf   = 1.0f;
            float4 q = g_pq[j];
            float d0  = __fsub_rn(q.x, p0);
            float d1  = __fsub_rn(q.y, p1);
            float d2v = __fsub_rn(q.z, p2);
            float sq = __fadd_rn(__fadd_rn(__fmul_rn(d0,d0), __fmul_rn(d1,d1)),
                                 __fmul_rn(d2v,d2v));
            wgt = (sq > 0.0f) ? __fsqrt_rn(sq) : 0.0f;
        }
        out[e]         = rowf;       // edge_index row
        out[E + e]     = (float)i;   // edge_index col
        out[2*E + e]   = wgt;        // edge_weight (mask applied)
        out[3*E + e]   = mf;         // mask
    }
    if (lane == 0) {                 // self-loop slot N*K + i
        long long se = (long long)N * KNN + i;
        out[se]         = (float)i;
        out[E + se]     = (float)i;
        out[2*E + se]   = 0.0f;
        out[3*E + se]   = 1.0f;
    }
}

extern "C" void kernel_launch(void* const* d_in, const int* in_sizes, int n_in,
                              void* d_out, int out_size) {
    const float* pos   = (const float*)d_in[0];
    const int*   batch = (const int*)d_in[1];
    float*       out   = (float*)d_out;

    int N = in_sizes[0] / 3;   // pos is [N,3] float32

    prep_kernel<<<PREPB, 256>>>(pos, batch, N);
    radius_graph_kernel<<<(N + WPB - 1) / WPB, WPB * 32>>>(batch, out, N);
}

// round 14
// speedup vs baseline: 1.3243x; 1.3243x over previous
#include <cuda_runtime.h>
#include <cuda_bf16.h>
#include <cstdint>

#define KNN   32
#define MAXC  128          // per-warp candidate cap (in-cutoff mean ~34)
#define NB    50           // z-bins per strip (width = 1.0)
#define NYB   5            // y-strips (width = 10.0)
#define NCB   (NYB * NB)   // bins per segment = 250
#define NSEG  8
#define GBINS (NSEG * NCB) // global bins = 2000
#define NMAX  8192
#define WPB   8            // worker warps per block (256 threads)
#define CCTAS 8            // CTAs per cluster (one cluster per segment)
#define PT    256          // threads per prep CTA

__device__ float4 g_pq [NMAX];          // original order: (p0,p1,p2,|p|^2)
__device__ float4 g_pqs[NMAX];          // globally bin-sorted
__device__ int    g_oidx[NMAX];         // sorted position -> original index
__device__ int    g_cum[GBINS + 1];     // absolute exclusive bin starts

__device__ __forceinline__ int z_bin(float z) {
    return min(NB - 1, max(0, (int)(z)));            // width 1.0
}
__device__ __forceinline__ int y_strip(float y) {
    return min(NYB - 1, max(0, (int)(y * 0.1f)));    // width 10.0
}

// Monotonic float->uint (handles tiny negative d2 from gram-trick rounding)
__device__ __forceinline__ unsigned int f2mono(float f) {
    unsigned int u = __float_as_uint(f);
    return (u & 0x80000000u) ? ~u : (u | 0x80000000u);
}

__device__ __forceinline__ uint32_t smem_u32(const void* p) {
    uint32_t a;
    asm("{ .reg .u64 t; cvta.to.shared.u64 t, %1; cvt.u32.u64 %0, t; }"
        : "=r"(a) : "l"(p));
    return a;
}
__device__ __forceinline__ uint32_t cta_rank() {
    uint32_t r; asm("mov.u32 %0, %%cluster_ctarank;" : "=r"(r)); return r;
}
__device__ __forceinline__ uint32_t mapa_rank(uint32_t laddr, uint32_t rank) {
    uint32_t r;
    asm("mapa.shared::cluster.u32 %0, %1, %2;" : "=r"(r) : "r"(laddr), "r"(rank));
    return r;
}
__device__ __forceinline__ int ld_dsmem(uint32_t addr) {
    int v;
    asm volatile("ld.shared::cluster.b32 %0, [%1];" : "=r"(v) : "r"(addr));
    return v;
}
#define CLUSTER_SYNC() do { \
    asm volatile("barrier.cluster.arrive.aligned;" ::: "memory"); \
    asm volatile("barrier.cluster.wait.aligned;"   ::: "memory"); \
} while (0)

// ---------------- Kernel 1: cluster-parallel per-segment (y,z)-bin sort.
// 8 clusters x 8 CTAs x 256 threads. Each CTA handles 1/8 of its segment;
// cross-CTA histogram exchange via DSMEM; scatter slots are deterministic
// (rank-exclusive offsets) so no cross-CTA atomics are needed.
__global__ void __launch_bounds__(PT) __cluster_dims__(CCTAS, 1, 1)
binsort_kernel(const float* __restrict__ pos,
               const int* __restrict__ batch, int N) {
    __shared__ int s_hist[NCB];
    __shared__ int s_cursor[NCB];
    __shared__ int s_part[PT / 32];
    __shared__ int s_lo, s_hi;

    const int seg  = blockIdx.x / CCTAS;
    const int rank = (int)cta_rank();
    const int tid  = threadIdx.x;
    const int lane = tid & 31;
    const int wid  = tid >> 5;

    if (tid == 0) { s_lo = 0; s_hi = 0; }
    for (int c = tid; c < NCB; c += PT) s_hist[c] = 0;
    __syncthreads();

    // redundant per-CTA segment bounds: count(batch < seg), count(batch <= seg)
    int clo = 0, chi = 0;
    for (int t = tid; t < N; t += PT) {
        int b = batch[t];
        clo += (b <  seg);
        chi += (b <= seg);
    }
    #pragma unroll
    for (int o = 16; o; o >>= 1) {
        clo += __shfl_down_sync(0xffffffffu, clo, o);
        chi += __shfl_down_sync(0xffffffffu, chi, o);
    }
    if (lane == 0) { atomicAdd(&s_lo, clo); atomicAdd(&s_hi, chi); }
    __syncthreads();

    const int lo  = s_lo;
    const int n   = s_hi - s_lo;
    const int per = (n + CCTAS - 1) / CCTAS;
    const int mylo = lo + rank * per;
    const int myhi = min(lo + n, mylo + per);

    // phase A: pack (pos,|p|^2) with reference rounding + LOCAL histogram
    for (int i = mylo + tid; i < myhi; i += PT) {
        float p0 = pos[3*i+0], p1 = pos[3*i+1], p2 = pos[3*i+2];
        float a = __fadd_rn(__fadd_rn(__fmul_rn(p0,p0), __fmul_rn(p1,p1)),
                            __fmul_rn(p2,p2));
        g_pq[i] = make_float4(p0, p1, p2, a);
        atomicAdd(&s_hist[y_strip(p1) * NB + z_bin(p2)], 1);
    }
    __syncthreads();
    CLUSTER_SYNC();                       // all CTAs' local hists now stable

    // phase B: gather peers' counts for bin `tid`, segment scan, cursors
    const uint32_t hbase = smem_u32(&s_hist[0]);
    int total = 0, myoff = 0;
    if (tid < NCB) {
        int pv[CCTAS];
        #pragma unroll
        for (int p = 0; p < CCTAS; p++)
            pv[p] = ld_dsmem(mapa_rank(hbase + tid * 4, (uint32_t)p));
        #pragma unroll
        for (int p = 0; p < CCTAS; p++) {
            total += pv[p];
            if (p < rank) myoff += pv[p];
        }
    }
    // block scan over `total` (250 live lanes of 256)
    int incl = total;
    #pragma unroll
    for (int o = 1; o < 32; o <<= 1) {
        int v = __shfl_up_sync(0xffffffffu, incl, o);
        if (lane >= o) incl += v;
    }
    if (lane == 31) s_part[wid] = incl;
    __syncthreads();
    int off = 0;
    #pragma unroll
    for (int p = 0; p < PT / 32; p++) off += (p < wid) ? s_part[p] : 0;
    const int excl = off + incl - total;
    if (tid < NCB) {
        s_cursor[tid] = lo + excl + myoff;      // this CTA's deterministic base
        if (rank == 0) g_cum[seg * NCB + tid] = lo + excl;
    }
    if (rank == 0 && tid == 0 && seg == NSEG - 1) g_cum[GBINS] = lo + n;
    __syncthreads();

    // phase C: scatter my slice (intra-CTA in-bin order nondeterministic --
    // output-invariant, selection keys carry the original index)
    for (int i = mylo + tid; i < myhi; i += PT) {
        float4 pq = g_pq[i];
        int bin = y_strip(pq.y) * NB + z_bin(pq.z);
        int slot = atomicAdd(&s_cursor[bin], 1);
        g_pqs [slot] = pq;
        g_oidx[slot] = i;
    }
    CLUSTER_SYNC();   // keep s_hist alive until all peers finish phase B reads
}

// ---------------- Kernel 2: one WARP per SORTED position (identical to R11-R13).
__global__ void __launch_bounds__(WPB * 32)
radius_graph_kernel(const int* __restrict__ batch,
                    float* __restrict__ out, int N) {
    __shared__ unsigned long long s_keys[WPB][MAXC];
    __shared__ unsigned long long s_sel [WPB][KNN];

    const int w    = threadIdx.x >> 5;
    const int lane = threadIdx.x & 31;
    const int s    = blockIdx.x * WPB + w;     // sorted position
    if (s >= N) return;                         // no block-level syncs below

    const int b  = batch[s];        // global sort keeps segments contiguous
    const int cb = b * NCB;

    const float4 pc = g_pqs[s];     // same bits as g_pq[i]
    const int   i  = g_oidx[s];     // original node index
    const float p0 = pc.x, p1 = pc.y, p2 = pc.z, x2i = pc.w;

    // (y,z) bin ranges covering [+-10.01]: over-coverage strictly dominates
    // gram-trick rounding slack AND bin-boundary fp edges -> no false prunes.
    int bzlo = max(0,      (int)floorf(p2 - 10.01f));
    int bzhi = min(NB - 1, (int)floorf(p2 + 10.01f));
    int yslo = max(0,       (int)floorf((p1 - 10.01f) * 0.1f));
    int yshi = min(NYB - 1, (int)floorf((p1 + 10.01f) * 0.1f));

    // Phase 1: dual-candidate scan (64/warp-iter, MLP=2, 2 ballots).
    // Compaction order is irrelevant: keys unique, rank-select is a total order.
    int base = 0;
    for (int ys = yslo; ys <= yshi; ys++) {
        const int rlo = g_cum[cb + ys * NB + bzlo];       // absolute positions
        const int rhi = g_cum[cb + ys * NB + bzhi + 1];
        for (int rb = rlo; rb < rhi; rb += 64) {
            int r0 = rb + lane, r1 = rb + 32 + lane;
            int rc0 = min(r0, rhi - 1), rc1 = min(r1, rhi - 1);
            float4 q0 = g_pqs[rc0];
            float4 q1 = g_pqs[rc1];
            int   o0 = g_oidx[rc0];
            int   o1 = g_oidx[rc1];
            // d2 = (x2i + x2j) - 2*dot, exact reference rounding
            float dot0 = __fmaf_rn(p2, q0.z, __fmaf_rn(p1, q0.y, __fmul_rn(p0, q0.x)));
            float d20  = __fsub_rn(__fadd_rn(x2i, q0.w), __fmul_rn(2.0f, dot0));
            float dot1 = __fmaf_rn(p2, q1.z, __fmaf_rn(p1, q1.y, __fmul_rn(p0, q1.x)));
            float d21  = __fsub_rn(__fadd_rn(x2i, q1.w), __fmul_rn(2.0f, dot1));
            bool h0 = (r0 < rhi) && (d20 <= 100.0f) && (o0 != i);
            bool h1 = (r1 < rhi) && (d21 <= 100.0f) && (o1 != i);
            unsigned m0 = __ballot_sync(0xffffffffu, h0);
            unsigned m1 = __ballot_sync(0xffffffffu, h1);
            int c0 = __popc(m0);
            if (h0) {
                int slot = base + __popc(m0 & ((1u << lane) - 1u));
                if (slot < MAXC)
                    s_keys[w][slot] = ((unsigned long long)f2mono(d20) << 32)
                                    | (unsigned int)o0;
            }
            if (h1) {
                int slot = base + c0 + __popc(m1 & ((1u << lane) - 1u));
                if (slot < MAXC)
                    s_keys[w][slot] = ((unsigned long long)f2mono(d21) << 32)
                                    | (unsigned int)o1;
            }
            base += c0 + __popc(m1);
        }
    }
    const int M = min(base, MAXC);
    __syncwarp();

    // Phase 2: exact rank selection (keys unique; tie -> lower index, = lax.top_k)
    for (int e = lane; e < M; e += 32) {
        unsigned long long mykey = s_keys[w][e];
        int rank = 0;
        #pragma unroll 4
        for (int t = 0; t < M; t++) rank += (s_keys[w][t] < mykey) ? 1 : 0;
        if (rank < KNN) s_sel[w][rank] = mykey;
    }
    __syncwarp();

    const int Msel = min(M, KNN);
    const long long E = (long long)N * (KNN + 1);

    // Phase 3: lane k writes neighbor slot k (K == warp size)
    {
        const int k = lane;
        long long e = (long long)i * KNN + k;
        float rowf = 0.0f, wgt = 0.0f, mf = 0.0f;
        if (k < Msel) {
            unsigned long long key = s_sel[w][k];
            int j = (int)(key & 0xFFFFFFFFull);
            rowf = (float)j;
            mf   = 1.0f;
            float4 q = g_pq[j];
            float d0  = __fsub_rn(q.x, p0);
            float d1  = __fsub_rn(q.y, p1);
            float d2v = __fsub_rn(q.z, p2);
            float sq = __fadd_rn(__fadd_rn(__fmul_rn(d0,d0), __fmul_rn(d1,d1)),
                                 __fmul_rn(d2v,d2v));
            wgt = (sq > 0.0f) ? __fsqrt_rn(sq) : 0.0f;
        }
        out[e]         = rowf;       // edge_index row
        out[E + e]     = (float)i;   // edge_index col
        out[2*E + e]   = wgt;        // edge_weight (mask applied)
        out[3*E + e]   = mf;         // mask
    }
    if (lane == 0) {                 // self-loop slot N*K + i
        long long se = (long long)N * KNN + i;
        out[se]         = (float)i;
        out[E + se]     = (float)i;
        out[2*E + se]   = 0.0f;
        out[3*E + se]   = 1.0f;
    }
}

extern "C" void kernel_launch(void* const* d_in, const int* in_sizes, int n_in,
                              void* d_out, int out_size) {
    const float* pos   = (const float*)d_in[0];
    const int*   batch = (const int*)d_in[1];
    float*       out   = (float*)d_out;

    int N = in_sizes[0] / 3;   // pos is [N,3] float32

    binsort_kernel<<<NSEG * CCTAS, PT>>>(pos, batch, N);
    radius_graph_kernel<<<(N + WPB - 1) / WPB, WPB * 32>>>(batch, out, N);
}

// round 15
// speedup vs baseline: 1.4792x; 1.1170x over previous
#include <cuda_runtime.h>
#include <cuda_bf16.h>
#include <cstdint>

#define KNN   32
#define MAXC  128          // per-warp candidate cap (in-cutoff mean ~34)
#define NB    50           // z-bins per strip (width = 1.0)
#define NYB   5            // y-strips (width = 10.0)
#define NCB   (NYB * NB)   // bins per segment = 250
#define NSEG  8
#define GBINS (NSEG * NCB) // global bins = 2000
#define NMAX  8192
#define PAD   64           // scan overrun padding (zeros; predicated off)
#define WPB   8            // worker warps per block (256 threads)
#define CCTAS 8            // CTAs per cluster (one cluster per segment)
#define PT    256          // threads per prep CTA

__device__ float4 g_pq [NMAX];          // original order: (p0,p1,p2,|p|^2)
__device__ float4 g_pqs[NMAX + PAD];    // sorted: (p0,p1,p2, idx-bits); pad zeros
__device__ int    g_cum[GBINS + 1];     // absolute exclusive bin starts

__device__ __forceinline__ int z_bin(float z) {
    return min(NB - 1, max(0, (int)(z)));            // width 1.0
}
__device__ __forceinline__ int y_strip(float y) {
    return min(NYB - 1, max(0, (int)(y * 0.1f)));    // width 10.0
}

// Monotonic float->uint (handles tiny negative d2 from gram-trick rounding)
__device__ __forceinline__ unsigned int f2mono(float f) {
    unsigned int u = __float_as_uint(f);
    return (u & 0x80000000u) ? ~u : (u | 0x80000000u);
}

// Reference-rounded squared norm: (x*x + y*y) + z*z, no FMA contraction.
__device__ __forceinline__ float ref_x2(float x, float y, float z) {
    return __fadd_rn(__fadd_rn(__fmul_rn(x,x), __fmul_rn(y,y)), __fmul_rn(z,z));
}

__device__ __forceinline__ uint32_t smem_u32(const void* p) {
    uint32_t a;
    asm("{ .reg .u64 t; cvta.to.shared.u64 t, %1; cvt.u32.u64 %0, t; }"
        : "=r"(a) : "l"(p));
    return a;
}
__device__ __forceinline__ uint32_t cta_rank() {
    uint32_t r; asm("mov.u32 %0, %%cluster_ctarank;" : "=r"(r)); return r;
}
__device__ __forceinline__ uint32_t mapa_rank(uint32_t laddr, uint32_t rank) {
    uint32_t r;
    asm("mapa.shared::cluster.u32 %0, %1, %2;" : "=r"(r) : "r"(laddr), "r"(rank));
    return r;
}
__device__ __forceinline__ int ld_dsmem(uint32_t addr) {
    int v;
    asm volatile("ld.shared::cluster.b32 %0, [%1];" : "=r"(v) : "r"(addr));
    return v;
}
#define CLUSTER_SYNC() do { \
    asm volatile("barrier.cluster.arrive.aligned;" ::: "memory"); \
    asm volatile("barrier.cluster.wait.aligned;"   ::: "memory"); \
} while (0)

// ---------------- Kernel 1: cluster-parallel per-segment (y,z)-bin sort.
// 8 clusters x 8 CTAs x 256 threads; DSMEM histogram exchange; deterministic
// rank-exclusive scatter bases (no cross-CTA atomics).
__global__ void __launch_bounds__(PT) __cluster_dims__(CCTAS, 1, 1)
binsort_kernel(const float* __restrict__ pos,
               const int* __restrict__ batch, int N) {
    __shared__ int s_hist[NCB];
    __shared__ int s_cursor[NCB];
    __shared__ int s_part[PT / 32];
    __shared__ int s_lo, s_hi;

    const int seg  = blockIdx.x / CCTAS;
    const int rank = (int)cta_rank();
    const int tid  = threadIdx.x;
    const int lane = tid & 31;
    const int wid  = tid >> 5;

    if (tid == 0) { s_lo = 0; s_hi = 0; }
    for (int c = tid; c < NCB; c += PT) s_hist[c] = 0;
    __syncthreads();

    // redundant per-CTA segment bounds: count(batch < seg), count(batch <= seg)
    int clo = 0, chi = 0;
    for (int t = tid; t < N; t += PT) {
        int b = batch[t];
        clo += (b <  seg);
        chi += (b <= seg);
    }
    #pragma unroll
    for (int o = 16; o; o >>= 1) {
        clo += __shfl_down_sync(0xffffffffu, clo, o);
        chi += __shfl_down_sync(0xffffffffu, chi, o);
    }
    if (lane == 0) { atomicAdd(&s_lo, clo); atomicAdd(&s_hi, chi); }
    __syncthreads();

    const int lo  = s_lo;
    const int n   = s_hi - s_lo;
    const int per = (n + CCTAS - 1) / CCTAS;
    const int mylo = lo + rank * per;
    const int myhi = min(lo + n, mylo + per);

    // phase A: pack (pos,|p|^2) with reference rounding + LOCAL histogram
    for (int i = mylo + tid; i < myhi; i += PT) {
        float p0 = pos[3*i+0], p1 = pos[3*i+1], p2 = pos[3*i+2];
        g_pq[i] = make_float4(p0, p1, p2, ref_x2(p0, p1, p2));
        atomicAdd(&s_hist[y_strip(p1) * NB + z_bin(p2)], 1);
    }
    __syncthreads();
    CLUSTER_SYNC();                       // all CTAs' local hists now stable

    // phase B: gather peers' counts for bin `tid`, segment scan, cursors
    const uint32_t hbase = smem_u32(&s_hist[0]);
    int total = 0, myoff = 0;
    if (tid < NCB) {
        int pv[CCTAS];
        #pragma unroll
        for (int p = 0; p < CCTAS; p++)
            pv[p] = ld_dsmem(mapa_rank(hbase + tid * 4, (uint32_t)p));
        #pragma unroll
        for (int p = 0; p < CCTAS; p++) {
            total += pv[p];
            if (p < rank) myoff += pv[p];
        }
    }
    int incl = total;
    #pragma unroll
    for (int o = 1; o < 32; o <<= 1) {
        int v = __shfl_up_sync(0xffffffffu, incl, o);
        if (lane >= o) incl += v;
    }
    if (lane == 31) s_part[wid] = incl;
    __syncthreads();
    int off = 0;
    #pragma unroll
    for (int p = 0; p < PT / 32; p++) off += (p < wid) ? s_part[p] : 0;
    const int excl = off + incl - total;
    if (tid < NCB) {
        s_cursor[tid] = lo + excl + myoff;      // this CTA's deterministic base
        if (rank == 0) g_cum[seg * NCB + tid] = lo + excl;
    }
    if (rank == 0 && tid == 0 && seg == NSEG - 1) g_cum[GBINS] = lo + n;
    __syncthreads();

    // phase C: scatter my slice; candidate record = (x,y,z, idx-bits).
    // Intra-CTA in-bin order nondeterministic -- output-invariant (keys carry
    // the original index; rank selection is a total order).
    for (int i = mylo + tid; i < myhi; i += PT) {
        float4 pq = g_pq[i];
        int bin = y_strip(pq.y) * NB + z_bin(pq.z);
        int slot = atomicAdd(&s_cursor[bin], 1);
        g_pqs[slot] = make_float4(pq.x, pq.y, pq.z, __uint_as_float((unsigned)i));
    }
    CLUSTER_SYNC();   // keep s_hist alive until all peers finish phase B reads
}

// ---------------- Kernel 2: one WARP per SORTED position.
__global__ void __launch_bounds__(WPB * 32)
radius_graph_kernel(const int* __restrict__ batch,
                    float* __restrict__ out, int N) {
    __shared__ unsigned long long s_keys[WPB][MAXC];
    __shared__ unsigned long long s_sel [WPB][KNN];

    const int w    = threadIdx.x >> 5;
    const int lane = threadIdx.x & 31;
    const int s    = blockIdx.x * WPB + w;     // sorted position
    if (s >= N) return;                         // no block-level syncs below

    const int b  = batch[s];        // global sort keeps segments contiguous
    const int cb = b * NCB;

    const float4 pc = g_pqs[s];
    const int   i  = (int)__float_as_uint(pc.w);   // original node index
    const float p0 = pc.x, p1 = pc.y, p2 = pc.z;
    const float x2i = ref_x2(p0, p1, p2);          // identical bits to g_pq[i].w

    // (y,z) bin ranges covering [+-10.01]: over-coverage strictly dominates
    // gram-trick rounding slack AND bin-boundary fp edges -> no false prunes.
    int bzlo = max(0,      (int)floorf(p2 - 10.01f));
    int bzhi = min(NB - 1, (int)floorf(p2 + 10.01f));
    int yslo = max(0,       (int)floorf((p1 - 10.01f) * 0.1f));
    int yshi = min(NYB - 1, (int)floorf((p1 + 10.01f) * 0.1f));

    // Phase 1: dual-candidate scan (64/warp-iter, MLP=2, 2 ballots).
    // No tail clamp: g_pqs has PAD zero entries; OOB lanes predicated off.
    int base = 0;
    for (int ys = yslo; ys <= yshi; ys++) {
        const int rlo = g_cum[cb + ys * NB + bzlo];       // absolute positions
        const int rhi = g_cum[cb + ys * NB + bzhi + 1];
        for (int rb = rlo; rb < rhi; rb += 64) {
            int r0 = rb + lane, r1 = rb + 32 + lane;
            float4 q0 = g_pqs[r0];
            float4 q1 = g_pqs[r1];
            int   o0 = (int)__float_as_uint(q0.w);
            int   o1 = (int)__float_as_uint(q1.w);
            // x2j recomputed with the exact reference rounding sequence
            float x20 = ref_x2(q0.x, q0.y, q0.z);
            float x21 = ref_x2(q1.x, q1.y, q1.z);
            // d2 = (x2i + x2j) - 2*dot, exact reference rounding
            float dot0 = __fmaf_rn(p2, q0.z, __fmaf_rn(p1, q0.y, __fmul_rn(p0, q0.x)));
            float d20  = __fsub_rn(__fadd_rn(x2i, x20), __fmul_rn(2.0f, dot0));
            float dot1 = __fmaf_rn(p2, q1.z, __fmaf_rn(p1, q1.y, __fmul_rn(p0, q1.x)));
            float d21  = __fsub_rn(__fadd_rn(x2i, x21), __fmul_rn(2.0f, dot1));
            bool h0 = (r0 < rhi) && (d20 <= 100.0f) && (o0 != i);
            bool h1 = (r1 < rhi) && (d21 <= 100.0f) && (o1 != i);
            unsigned m0 = __ballot_sync(0xffffffffu, h0);
            unsigned m1 = __ballot_sync(0xffffffffu, h1);
            int c0 = __popc(m0);
            if (h0) {
                int slot = base + __popc(m0 & ((1u << lane) - 1u));
                if (slot < MAXC)
                    s_keys[w][slot] = ((unsigned long long)f2mono(d20) << 32)
                                    | (unsigned int)o0;
            }
            if (h1) {
                int slot = base + c0 + __popc(m1 & ((1u << lane) - 1u));
                if (slot < MAXC)
                    s_keys[w][slot] = ((unsigned long long)f2mono(d21) << 32)
                                    | (unsigned int)o1;
            }
            base += c0 + __popc(m1);
        }
    }
    const int M = min(base, MAXC);
    __syncwarp();

    // Phase 2: exact rank selection (keys unique; tie -> lower index, = lax.top_k)
    for (int e = lane; e < M; e += 32) {
        unsigned long long mykey = s_keys[w][e];
        int rank = 0;
        #pragma unroll 8
        for (int t = 0; t < M; t++) rank += (s_keys[w][t] < mykey) ? 1 : 0;
        if (rank < KNN) s_sel[w][rank] = mykey;
    }
    __syncwarp();

    const int Msel = min(M, KNN);
    const long long E = (long long)N * (KNN + 1);

    // Phase 3: lane k writes neighbor slot k (K == warp size)
    {
        const int k = lane;
        long long e = (long long)i * KNN + k;
        float rowf = 0.0f, wgt = 0.0f, mf = 0.0f;
        if (k < Msel) {
            unsigned long long key = s_sel[w][k];
            int j = (int)(key & 0xFFFFFFFFull);
            rowf = (float)j;
            mf   = 1.0f;
            float4 q = g_pq[j];
            float d0  = __fsub_rn(q.x, p0);
            float d1  = __fsub_rn(q.y, p1);
            float d2v = __fsub_rn(q.z, p2);
            float sq = __fadd_rn(__fadd_rn(__fmul_rn(d0,d0), __fmul_rn(d1,d1)),
                                 __fmul_rn(d2v,d2v));
            wgt = (sq > 0.0f) ? __fsqrt_rn(sq) : 0.0f;
        }
        out[e]         = rowf;       // edge_index row
        out[E + e]     = (float)i;   // edge_index col
        out[2*E + e]   = wgt;        // edge_weight (mask applied)
        out[3*E + e]   = mf;         // mask
    }
    if (lane == 0) {                 // self-loop slot N*K + i
        long long se = (long long)N * KNN + i;
        out[se]         = (float)i;
        out[E + se]     = (float)i;
        out[2*E + se]   = 0.0f;
        out[3*E + se]   = 1.0f;
    }
}

extern "C" void kernel_launch(void* const* d_in, const int* in_sizes, int n_in,
                              void* d_out, int out_size) {
    const float* pos   = (const float*)d_in[0];
    const int*   batch = (const int*)d_in[1];
    float*       out   = (float*)d_out;

    int N = in_sizes[0] / 3;   // pos is [N,3] float32

    binsort_kernel<<<NSEG * CCTAS, PT>>>(pos, batch, N);
    radius_graph_kernel<<<(N + WPB - 1) / WPB, WPB * 32>>>(batch, out, N);
}

// round 16
// speedup vs baseline: 1.4848x; 1.0038x over previous
#include <cuda_runtime.h>
#include <cuda_bf16.h>
#include <cstdint>

#define KNN   32
#define MAXC  128          // per-warp candidate cap (in-cutoff mean ~34)
#define NB    50           // z-bins per strip (width = 1.0)
#define NYB   5            // y-strips (width = 10.0)
#define NCB   (NYB * NB)   // bins per segment = 250
#define NSEG  8
#define GBINS (NSEG * NCB) // global bins = 2000
#define NMAX  8192
#define PAD   64           // scan overrun padding (zeros; predicated off)
#define WPB   8            // worker warps per block (256 threads)
#define CCTAS 8            // CTAs per cluster (one cluster per segment)
#define PT    256          // threads per prep CTA

__device__ float4 g_pq [NMAX];          // original order: (p0,p1,p2,|p|^2)
__device__ float4 g_pqs[NMAX + PAD];    // sorted: (p0,p1,p2, idx-bits); pad zeros
__device__ int    g_cum[GBINS + 1];     // absolute exclusive bin starts

__device__ __forceinline__ int z_bin(float z) {
    return min(NB - 1, max(0, (int)(z)));            // width 1.0
}
__device__ __forceinline__ int y_strip(float y) {
    return min(NYB - 1, max(0, (int)(y * 0.1f)));    // width 10.0
}

// Monotonic float->uint (handles tiny negative d2 from gram-trick rounding)
__device__ __forceinline__ unsigned int f2mono(float f) {
    unsigned int u = __float_as_uint(f);
    return (u & 0x80000000u) ? ~u : (u | 0x80000000u);
}

// Reference-rounded squared norm: (x*x + y*y) + z*z, no FMA contraction.
__device__ __forceinline__ float ref_x2(float x, float y, float z) {
    return __fadd_rn(__fadd_rn(__fmul_rn(x,x), __fmul_rn(y,y)), __fmul_rn(z,z));
}

__device__ __forceinline__ uint32_t smem_u32(const void* p) {
    uint32_t a;
    asm("{ .reg .u64 t; cvta.to.shared.u64 t, %1; cvt.u32.u64 %0, t; }"
        : "=r"(a) : "l"(p));
    return a;
}
__device__ __forceinline__ uint32_t cta_rank() {
    uint32_t r; asm("mov.u32 %0, %%cluster_ctarank;" : "=r"(r)); return r;
}
__device__ __forceinline__ uint32_t mapa_rank(uint32_t laddr, uint32_t rank) {
    uint32_t r;
    asm("mapa.shared::cluster.u32 %0, %1, %2;" : "=r"(r) : "r"(laddr), "r"(rank));
    return r;
}
__device__ __forceinline__ int ld_dsmem(uint32_t addr) {
    int v;
    asm volatile("ld.shared::cluster.b32 %0, [%1];" : "=r"(v) : "r"(addr));
    return v;
}
#define CLUSTER_SYNC() do { \
    asm volatile("barrier.cluster.arrive.aligned;" ::: "memory"); \
    asm volatile("barrier.cluster.wait.aligned;"   ::: "memory"); \
} while (0)

// ---------------- Kernel 1: cluster-parallel per-segment (y,z)-bin sort.
// 8 clusters x 8 CTAs x 256 threads; DSMEM histogram exchange; deterministic
// rank-exclusive scatter bases (no cross-CTA atomics). Identical to R15.
__global__ void __launch_bounds__(PT) __cluster_dims__(CCTAS, 1, 1)
binsort_kernel(const float* __restrict__ pos,
               const int* __restrict__ batch, int N) {
    __shared__ int s_hist[NCB];
    __shared__ int s_cursor[NCB];
    __shared__ int s_part[PT / 32];
    __shared__ int s_lo, s_hi;

    const int seg  = blockIdx.x / CCTAS;
    const int rank = (int)cta_rank();
    const int tid  = threadIdx.x;
    const int lane = tid & 31;
    const int wid  = tid >> 5;

    if (tid == 0) { s_lo = 0; s_hi = 0; }
    for (int c = tid; c < NCB; c += PT) s_hist[c] = 0;
    __syncthreads();

    // redundant per-CTA segment bounds: count(batch < seg), count(batch <= seg)
    int clo = 0, chi = 0;
    for (int t = tid; t < N; t += PT) {
        int b = batch[t];
        clo += (b <  seg);
        chi += (b <= seg);
    }
    #pragma unroll
    for (int o = 16; o; o >>= 1) {
        clo += __shfl_down_sync(0xffffffffu, clo, o);
        chi += __shfl_down_sync(0xffffffffu, chi, o);
    }
    if (lane == 0) { atomicAdd(&s_lo, clo); atomicAdd(&s_hi, chi); }
    __syncthreads();

    const int lo  = s_lo;
    const int n   = s_hi - s_lo;
    const int per = (n + CCTAS - 1) / CCTAS;
    const int mylo = lo + rank * per;
    const int myhi = min(lo + n, mylo + per);

    // phase A: pack (pos,|p|^2) with reference rounding + LOCAL histogram
    for (int i = mylo + tid; i < myhi; i += PT) {
        float p0 = pos[3*i+0], p1 = pos[3*i+1], p2 = pos[3*i+2];
        g_pq[i] = make_float4(p0, p1, p2, ref_x2(p0, p1, p2));
        atomicAdd(&s_hist[y_strip(p1) * NB + z_bin(p2)], 1);
    }
    __syncthreads();
    CLUSTER_SYNC();                       // all CTAs' local hists now stable

    // phase B: gather peers' counts for bin `tid`, segment scan, cursors
    const uint32_t hbase = smem_u32(&s_hist[0]);
    int total = 0, myoff = 0;
    if (tid < NCB) {
        int pv[CCTAS];
        #pragma unroll
        for (int p = 0; p < CCTAS; p++)
            pv[p] = ld_dsmem(mapa_rank(hbase + tid * 4, (uint32_t)p));
        #pragma unroll
        for (int p = 0; p < CCTAS; p++) {
            total += pv[p];
            if (p < rank) myoff += pv[p];
        }
    }
    int incl = total;
    #pragma unroll
    for (int o = 1; o < 32; o <<= 1) {
        int v = __shfl_up_sync(0xffffffffu, incl, o);
        if (lane >= o) incl += v;
    }
    if (lane == 31) s_part[wid] = incl;
    __syncthreads();
    int off = 0;
    #pragma unroll
    for (int p = 0; p < PT / 32; p++) off += (p < wid) ? s_part[p] : 0;
    const int excl = off + incl - total;
    if (tid < NCB) {
        s_cursor[tid] = lo + excl + myoff;      // this CTA's deterministic base
        if (rank == 0) g_cum[seg * NCB + tid] = lo + excl;
    }
    if (rank == 0 && tid == 0 && seg == NSEG - 1) g_cum[GBINS] = lo + n;
    __syncthreads();

    // phase C: scatter my slice; candidate record = (x,y,z, idx-bits).
    // Intra-CTA in-bin order nondeterministic -- output-invariant (keys carry
    // the original index; rank selection is a total order).
    for (int i = mylo + tid; i < myhi; i += PT) {
        float4 pq = g_pq[i];
        int bin = y_strip(pq.y) * NB + z_bin(pq.z);
        int slot = atomicAdd(&s_cursor[bin], 1);
        g_pqs[slot] = make_float4(pq.x, pq.y, pq.z, __uint_as_float((unsigned)i));
    }
    CLUSTER_SYNC();   // keep s_hist alive until all peers finish phase B reads
}

// ---------------- Kernel 2: one WARP per sorted position, STRIDED mapping:
// warp w of block blk handles s = w*numBlocks + blk, so each block mixes 8
// different z-regions -> near-uniform per-block work (kills the one-wave tail).
__global__ void __launch_bounds__(WPB * 32)
radius_graph_kernel(const int* __restrict__ batch,
                    float* __restrict__ out, int N) {
    __shared__ unsigned long long s_keys[WPB][MAXC];
    __shared__ unsigned long long s_sel [WPB][KNN];

    const int w    = threadIdx.x >> 5;
    const int lane = threadIdx.x & 31;
    const int s    = w * (int)gridDim.x + blockIdx.x;   // strided sorted position
    if (s >= N) return;                                  // no block syncs below

    const int b  = batch[s];        // global sort keeps segments contiguous
    const int cb = b * NCB;

    const float4 pc = g_pqs[s];
    const int   i  = (int)__float_as_uint(pc.w);   // original node index
    const float p0 = pc.x, p1 = pc.y, p2 = pc.z;
    const float x2i = ref_x2(p0, p1, p2);          // identical bits to g_pq[i].w

    // (y,z) bin ranges covering [+-10.01]: over-coverage strictly dominates
    // gram-trick rounding slack AND bin-boundary fp edges -> no false prunes.
    int bzlo = max(0,      (int)floorf(p2 - 10.01f));
    int bzhi = min(NB - 1, (int)floorf(p2 + 10.01f));
    int yslo = max(0,       (int)floorf((p1 - 10.01f) * 0.1f));
    int yshi = min(NYB - 1, (int)floorf((p1 + 10.01f) * 0.1f));

    // Phase 1: dual-candidate scan (64/warp-iter, MLP=2, 2 ballots).
    // No tail clamp: g_pqs has PAD zero entries; OOB lanes predicated off.
    int base = 0;
    for (int ys = yslo; ys <= yshi; ys++) {
        const int rlo = g_cum[cb + ys * NB + bzlo];       // absolute positions
        const int rhi = g_cum[cb + ys * NB + bzhi + 1];
        for (int rb = rlo; rb < rhi; rb += 64) {
            int r0 = rb + lane, r1 = rb + 32 + lane;
            float4 q0 = g_pqs[r0];
            float4 q1 = g_pqs[r1];
            int   o0 = (int)__float_as_uint(q0.w);
            int   o1 = (int)__float_as_uint(q1.w);
            // x2j recomputed with the exact reference rounding sequence
            float x20 = ref_x2(q0.x, q0.y, q0.z);
            float x21 = ref_x2(q1.x, q1.y, q1.z);
            // d2 = (x2i + x2j) - 2*dot, exact reference rounding
            float dot0 = __fmaf_rn(p2, q0.z, __fmaf_rn(p1, q0.y, __fmul_rn(p0, q0.x)));
            float d20  = __fsub_rn(__fadd_rn(x2i, x20), __fmul_rn(2.0f, dot0));
            float dot1 = __fmaf_rn(p2, q1.z, __fmaf_rn(p1, q1.y, __fmul_rn(p0, q1.x)));
            float d21  = __fsub_rn(__fadd_rn(x2i, x21), __fmul_rn(2.0f, dot1));
            bool h0 = (r0 < rhi) && (d20 <= 100.0f) && (o0 != i);
            bool h1 = (r1 < rhi) && (d21 <= 100.0f) && (o1 != i);
            unsigned m0 = __ballot_sync(0xffffffffu, h0);
            unsigned m1 = __ballot_sync(0xffffffffu, h1);
            int c0 = __popc(m0);
            if (h0) {
                int slot = base + __popc(m0 & ((1u << lane) - 1u));
                if (slot < MAXC)
                    s_keys[w][slot] = ((unsigned long long)f2mono(d20) << 32)
                                    | (unsigned int)o0;
            }
            if (h1) {
                int slot = base + c0 + __popc(m1 & ((1u << lane) - 1u));
                if (slot < MAXC)
                    s_keys[w][slot] = ((unsigned long long)f2mono(d21) << 32)
                                    | (unsigned int)o1;
            }
            base += c0 + __popc(m1);
        }
    }
    const int M = min(base, MAXC);
    __syncwarp();

    // Phase 2: exact rank selection (keys unique; tie -> lower index, = lax.top_k)
    for (int e = lane; e < M; e += 32) {
        unsigned long long mykey = s_keys[w][e];
        int rank = 0;
        #pragma unroll 8
        for (int t = 0; t < M; t++) rank += (s_keys[w][t] < mykey) ? 1 : 0;
        if (rank < KNN) s_sel[w][rank] = mykey;
    }
    __syncwarp();

    const int Msel = min(M, KNN);
    const long long E = (long long)N * (KNN + 1);

    // Phase 3: lane k writes neighbor slot k (K == warp size)
    {
        const int k = lane;
        long long e = (long long)i * KNN + k;
        float rowf = 0.0f, wgt = 0.0f, mf = 0.0f;
        if (k < Msel) {
            unsigned long long key = s_sel[w][k];
            int j = (int)(key & 0xFFFFFFFFull);
            rowf = (float)j;
            mf   = 1.0f;
            float4 q = g_pq[j];
            float d0  = __fsub_rn(q.x, p0);
            float d1  = __fsub_rn(q.y, p1);
            float d2v = __fsub_rn(q.z, p2);
            float sq = __fadd_rn(__fadd_rn(__fmul_rn(d0,d0), __fmul_rn(d1,d1)),
                                 __fmul_rn(d2v,d2v));
            wgt = (sq > 0.0f) ? __fsqrt_rn(sq) : 0.0f;
        }
        out[e]         = rowf;       // edge_index row
        out[E + e]     = (float)i;   // edge_index col
        out[2*E + e]   = wgt;        // edge_weight (mask applied)
        out[3*E + e]   = mf;         // mask
    }
    if (lane == 0) {                 // self-loop slot N*K + i
        long long se = (long long)N * KNN + i;
        out[se]         = (float)i;
        out[E + se]     = (float)i;
        out[2*E + se]   = 0.0f;
        out[3*E + se]   = 1.0f;
    }
}

extern "C" void kernel_launch(void* const* d_in, const int* in_sizes, int n_in,
                              void* d_out, int out_size) {
    const float* pos   = (const float*)d_in[0];
    const int*   batch = (const int*)d_in[1];
    float*       out   = (float*)d_out;

    int N = in_sizes[0] / 3;   // pos is [N,3] float32

    binsort_kernel<<<NSEG * CCTAS, PT>>>(pos, batch, N);
    radius_graph_kernel<<<(N + WPB - 1) / WPB, WPB * 32>>>(batch, out, N);
}